// round 6
// baseline (speedup 1.0000x reference)
#include <cuda_runtime.h>
#include <cuda_bf16.h>
#include <cstddef>

// Problem constants
#define NN_ 4096        // nodes (also OUT_F)
#define FRAW 512
#define INF 1024
#define OUTF 4096

// Scratch (device globals — no allocation allowed)
__device__ float g_x [(size_t)NN_ * INF];    // 16 MB
__device__ float g_wf[(size_t)NN_ * OUTF];   // 64 MB
__device__ float g_P [(size_t)NN_ * NN_];    // 64 MB  (masked G)
__device__ float g_PW[(size_t)NN_ * OUTF];   // 64 MB

// ---------------------------------------------------------------------------
// Packed fp32x2 helpers (Blackwell FFMA2 — only reachable via PTX f32x2 ops)
// ---------------------------------------------------------------------------
__device__ __forceinline__ unsigned long long bcast2(float a) {
    unsigned long long r;
    asm("mov.b64 %0, {%1, %1};" : "=l"(r) : "f"(a));
    return r;
}
__device__ __forceinline__ void ffma2(unsigned long long& d,
                                      unsigned long long a,
                                      unsigned long long b) {
    asm("fma.rn.f32x2 %0, %1, %2, %0;" : "+l"(d) : "l"(a), "l"(b));
}
__device__ __forceinline__ float2 unpack2(unsigned long long v) {
    float2 r;
    asm("mov.b64 {%0, %1}, %2;" : "=f"(r.x), "=f"(r.y) : "l"(v));
    return r;
}

// ---------------------------------------------------------------------------
// Generic tiled SGEMM: C[M,N] = A_logical[M,K] @ B_logical[K,N]
//   TA=false: A stored row-major (M,K);  TA=true: stored (K,M) (A_logical = ^T)
//   TB=false: B stored row-major (K,N);  TB=true: stored (N,K)
//   BIAS : C[i,j] += bias[j]
//   MASKT: C[i,j] *= maskT[j*M + i]
// Block tile 128x128, K-tile 8, 256 threads, 8x8 per thread.
// Double-buffered smem; inner product via packed fma.rn.f32x2.
// Requires M%128==0, N%128==0, K%8==0 (true for all call sites here).
// ---------------------------------------------------------------------------
template<bool TA, bool TB, bool BIAS, bool MASKT>
__global__ __launch_bounds__(256)
void gemm128(const float* __restrict__ A, const float* __restrict__ B,
             float* __restrict__ C, int M, int N, int K,
             const float* __restrict__ bias, const float* __restrict__ maskT)
{
    __shared__ float As[2][8][128];
    __shared__ float Bs[2][8][128];

    const int tid  = threadIdx.x;
    const int row0 = blockIdx.y * 128;
    const int col0 = blockIdx.x * 128;
    const int ty   = tid >> 4;   // 0..15 -> rows ty*8..ty*8+7
    const int tx   = tid & 15;   // 0..15 -> cols tx*8..tx*8+7

    // 8 rows x 4 column-pairs of packed f32x2 accumulators
    unsigned long long acc2[8][4];
#pragma unroll
    for (int i = 0; i < 8; i++)
#pragma unroll
        for (int jp = 0; jp < 4; jp++) acc2[i][jp] = 0ull;

    auto ldA = [&](int k0) -> float4 {
        if (!TA) {
            const int r  = tid >> 1;
            const int kq = (tid & 1) << 2;
            return *reinterpret_cast<const float4*>(
                &A[(size_t)(row0 + r) * K + (k0 + kq)]);
        } else {
            const int kk = tid >> 5;
            const int iq = (tid & 31) << 2;
            return *reinterpret_cast<const float4*>(
                &A[(size_t)(k0 + kk) * M + (row0 + iq)]);
        }
    };
    auto stA = [&](int buf, float4 v) {
        if (!TA) {
            const int r  = tid >> 1;
            const int kq = (tid & 1) << 2;
            As[buf][kq + 0][r] = v.x; As[buf][kq + 1][r] = v.y;
            As[buf][kq + 2][r] = v.z; As[buf][kq + 3][r] = v.w;
        } else {
            const int kk = tid >> 5;
            const int iq = (tid & 31) << 2;
            *reinterpret_cast<float4*>(&As[buf][kk][iq]) = v;
        }
    };
    auto ldB = [&](int k0) -> float4 {
        if (!TB) {
            const int kk = tid >> 5;
            const int jq = (tid & 31) << 2;
            return *reinterpret_cast<const float4*>(
                &B[(size_t)(k0 + kk) * N + (col0 + jq)]);
        } else {
            const int c  = tid >> 1;
            const int kq = (tid & 1) << 2;
            return *reinterpret_cast<const float4*>(
                &B[(size_t)(col0 + c) * K + (k0 + kq)]);
        }
    };
    auto stB = [&](int buf, float4 v) {
        if (!TB) {
            const int kk = tid >> 5;
            const int jq = (tid & 31) << 2;
            *reinterpret_cast<float4*>(&Bs[buf][kk][jq]) = v;
        } else {
            const int c  = tid >> 1;
            const int kq = (tid & 1) << 2;
            Bs[buf][kq + 0][c] = v.x; Bs[buf][kq + 1][c] = v.y;
            Bs[buf][kq + 2][c] = v.z; Bs[buf][kq + 3][c] = v.w;
        }
    };

    // Prologue: fill stage 0
    {
        float4 va = ldA(0), vb = ldB(0);
        stA(0, va); stB(0, vb);
    }
    __syncthreads();

    const int nk = K >> 3;
    for (int kt = 0; kt < nk; kt++) {
        const int buf  = kt & 1;
        const bool more = (kt + 1 < nk);
        float4 va, vb;
        if (more) { va = ldA((kt + 1) << 3); vb = ldB((kt + 1) << 3); }

        // ---- compute on stage `buf` ----
#pragma unroll
        for (int kk = 0; kk < 8; kk++) {
            const float4 a0 = *reinterpret_cast<const float4*>(&As[buf][kk][ty * 8 + 0]);
            const float4 a1 = *reinterpret_cast<const float4*>(&As[buf][kk][ty * 8 + 4]);
            // b column-pairs load directly as 64-bit lanes (no packing cost)
            const double2 b01 = *reinterpret_cast<const double2*>(&Bs[buf][kk][tx * 8 + 0]);
            const double2 b23 = *reinterpret_cast<const double2*>(&Bs[buf][kk][tx * 8 + 4]);
            const unsigned long long bp0 = __double_as_longlong(b01.x);
            const unsigned long long bp1 = __double_as_longlong(b01.y);
            const unsigned long long bp2 = __double_as_longlong(b23.x);
            const unsigned long long bp3 = __double_as_longlong(b23.y);
            const float av[8] = {a0.x, a0.y, a0.z, a0.w, a1.x, a1.y, a1.z, a1.w};
#pragma unroll
            for (int i = 0; i < 8; i++) {
                const unsigned long long ap = bcast2(av[i]);
                ffma2(acc2[i][0], ap, bp0);
                ffma2(acc2[i][1], ap, bp1);
                ffma2(acc2[i][2], ap, bp2);
                ffma2(acc2[i][3], ap, bp3);
            }
        }

        if (more) { stA(buf ^ 1, va); stB(buf ^ 1, vb); }
        __syncthreads();
    }

    // ---- epilogue ----
#pragma unroll
    for (int i = 0; i < 8; i++) {
        const int row = row0 + ty * 8 + i;
#pragma unroll
        for (int jp = 0; jp < 4; jp++) {
            float2 v = unpack2(acc2[i][jp]);
            const int col = col0 + tx * 8 + jp * 2;
            if (BIAS) {
                v.x += bias[col];
                v.y += bias[col + 1];
            }
            if (MASKT) {
                v.x *= maskT[(size_t)(col + 0) * M + row];
                v.y *= maskT[(size_t)(col + 1) * M + row];
            }
            *reinterpret_cast<float2*>(&C[(size_t)row * N + col]) = v;
        }
    }
}

// ---------------------------------------------------------------------------
// out[k, j] = wf[j, k] * PW[j, k] / nc[k]^2      (transposed elementwise)
// Tiled 32x32 transpose through shared memory.
// ---------------------------------------------------------------------------
__global__ __launch_bounds__(256)
void finalize_kernel(const float* __restrict__ wf, const float* __restrict__ PW,
                     const float* __restrict__ nc, float* __restrict__ out)
{
    __shared__ float t[32][33];
    const int kb = blockIdx.x * 32;   // k (output row) tile
    const int jb = blockIdx.y * 32;   // j (output col) tile
    const int tx = threadIdx.x;       // 0..31
    const int ty = threadIdx.y;       // 0..7

#pragma unroll
    for (int r = 0; r < 32; r += 8) {
        const size_t idx = (size_t)(jb + ty + r) * NN_ + (kb + tx);
        t[ty + r][tx] = wf[idx] * PW[idx];
    }
    __syncthreads();
#pragma unroll
    for (int r = 0; r < 32; r += 8) {
        const int k = kb + ty + r;
        const float n = nc[k];
        const float inv = 1.0f / (n * n);
        out[(size_t)k * NN_ + (jb + tx)] = t[tx][ty + r] * inv;
    }
}

// ---------------------------------------------------------------------------
extern "C" void kernel_launch(void* const* d_in, const int* in_sizes, int n_in,
                              void* d_out, int out_size)
{
    const float* nf  = (const float*)d_in[0];  // (4096, 512)
    const float* adj = (const float*)d_in[1];  // (4096, 4096)
    // d_in[2] = mask_father — identical to adjacency_matrix, unused
    const float* nc  = (const float*)d_in[3];  // (4096, 1)
    const float* S   = (const float*)d_in[4];  // mask_hadamard (4096,1,4096) == S (4096,4096)
    const float* lw  = (const float*)d_in[5];  // (1024, 512)
    const float* lb  = (const float*)d_in[6];  // (1024,)
    const float* w   = (const float*)d_in[7];  // (1024, 4096)
    float* out = (float*)d_out;                // (4096, 4096)

    float *x, *wf, *P, *PW;
    cudaGetSymbolAddress((void**)&x,  g_x);
    cudaGetSymbolAddress((void**)&wf, g_wf);
    cudaGetSymbolAddress((void**)&P,  g_P);
    cudaGetSymbolAddress((void**)&PW, g_PW);

    const dim3 blk(256);

    // 1) x = NF @ Wl^T + b        (4096,1024,512), B stored (N,K) -> TB=true
    gemm128<false, true, true, false>
        <<<dim3(INF / 128, NN_ / 128), blk>>>(nf, lw, x, NN_, INF, FRAW, lb, nullptr);

    // 2) wf = x @ W               (4096,4096,1024)
    gemm128<false, false, false, false>
        <<<dim3(OUTF / 128, NN_ / 128), blk>>>(x, w, wf, NN_, OUTF, INF, nullptr, nullptr);

    // 3) P = (A^T @ A) * S^T      (4096,4096,4096), A operand transposed, mask fused
    gemm128<true, false, false, true>
        <<<dim3(NN_ / 128, NN_ / 128), blk>>>(adj, adj, P, NN_, NN_, NN_, nullptr, S);

    // 4) PW = P @ wf              (4096,4096,4096)
    gemm128<false, false, false, false>
        <<<dim3(OUTF / 128, NN_ / 128), blk>>>(P, wf, PW, NN_, OUTF, NN_, nullptr, nullptr);

    // 5) out[k,j] = wf[j,k]*PW[j,k]/nc[k]^2
    finalize_kernel<<<dim3(NN_ / 32, NN_ / 32), dim3(32, 8)>>>(wf, PW, nc, out);
}

// round 11
// speedup vs baseline: 4.3913x; 4.3913x over previous
#include <cuda_runtime.h>
#include <cuda_bf16.h>
#include <cstddef>
#include <cstdint>

// Problem constants
#define NN_ 4096
#define FRAW 512
#define INF 1024
#define OUTF 4096

// ---------------------------------------------------------------------------
// Scratch (device globals — no allocation allowed)
// ---------------------------------------------------------------------------
__device__ float         g_x   [(size_t)NN_ * INF];     // 16 MB
__device__ __nv_bfloat16 g_xh  [(size_t)NN_ * INF];     // 8 MB
__device__ __nv_bfloat16 g_xl  [(size_t)NN_ * INF];     // 8 MB
__device__ __nv_bfloat16 g_At  [(size_t)NN_ * NN_];     // 32 MB  A^T bf16
__device__ __nv_bfloat16 g_Wth [(size_t)OUTF * INF];    // 8 MB   W^T hi
__device__ __nv_bfloat16 g_Wtl [(size_t)OUTF * INF];    // 8 MB   W^T lo
__device__ float         g_wf  [(size_t)NN_ * OUTF];    // 64 MB  wf fp32 row-major
__device__ __nv_bfloat16 g_wfTh[(size_t)OUTF * NN_];    // 32 MB  wf^T hi
__device__ __nv_bfloat16 g_wfTl[(size_t)OUTF * NN_];    // 32 MB  wf^T lo
__device__ __nv_bfloat16 g_Q   [(size_t)NN_ * NN_];     // 32 MB  Q = G.*S (row-major) = P^T
__device__ __nv_bfloat16 g_Prm [(size_t)NN_ * NN_];     // 32 MB  P row-major bf16
__device__ float         g_PW  [(size_t)NN_ * OUTF];    // 64 MB  P@wf fp32 row-major

// ---------------------------------------------------------------------------
// mma.sync / ldmatrix helpers (sm_80+ features — valid for compute_103 PTX)
// ---------------------------------------------------------------------------
__device__ __forceinline__ uint32_t smem_u32(const void* p) {
    uint32_t a;
    asm("{ .reg .u64 t; cvta.to.shared.u64 t, %1; cvt.u32.u64 %0, t; }" : "=r"(a) : "l"(p));
    return a;
}

#define LDMX4(rr, addr) \
    asm volatile("ldmatrix.sync.aligned.m8n8.x4.shared.b16 {%0,%1,%2,%3}, [%4];" \
        : "=r"((rr)[0]), "=r"((rr)[1]), "=r"((rr)[2]), "=r"((rr)[3]) : "r"(addr))

#define MMA16816(c, a, b0, b1) \
    asm volatile("mma.sync.aligned.m16n8k16.row.col.f32.bf16.bf16.f32 " \
        "{%0,%1,%2,%3}, {%4,%5,%6,%7}, {%8,%9}, {%0,%1,%2,%3};" \
        : "+f"((c)[0]), "+f"((c)[1]), "+f"((c)[2]), "+f"((c)[3]) \
        : "r"((a)[0]), "r"((a)[1]), "r"((a)[2]), "r"((a)[3]), "r"(b0), "r"(b1))

// ---------------------------------------------------------------------------
// Tensor GEMM (HMMA): C[M,N] tile 128x128 = sum over up to 3 phases of Ap @ Bp^T
//   Ap row-major [M, kcP*64] bf16; Bp row-major [N, kcP*64] bf16 (NT form)
//   EPI 0: outH[m*NN_+n] = bf16(C * Smask[m*NN_+n])   (GEMM-3: Q = G.*S, aligned)
//   EPI 1: outF[m*NN_+n] = C                          (GEMM-2 / GEMM-4)
// 256 threads = 8 warps (2 x 4), warp tile 64x32, K-tile 32, double-buffered.
// ---------------------------------------------------------------------------
#define LDA 40   // padded row length (bf16) — conflict-free ldmatrix

template<int EPI>
__global__ __launch_bounds__(256, 1)
void tensor_gemm(const __nv_bfloat16* __restrict__ A0, const __nv_bfloat16* __restrict__ B0, int kc0,
                 const __nv_bfloat16* __restrict__ A1, const __nv_bfloat16* __restrict__ B1, int kc1,
                 const __nv_bfloat16* __restrict__ A2, const __nv_bfloat16* __restrict__ B2, int kc2,
                 float* __restrict__ outF, __nv_bfloat16* __restrict__ outH,
                 const float* __restrict__ Smask)
{
    __shared__ __nv_bfloat16 As[2][128 * LDA];   // 10 KB x 2
    __shared__ __nv_bfloat16 Bs[2][128 * LDA];   // 10 KB x 2

    const int tid = threadIdx.x;
    const int lid = tid & 31, wid = tid >> 5;
    const int wm = wid >> 2, wn = wid & 3;          // warp grid 2 x 4
    const int m0 = blockIdx.y * 128, n0 = blockIdx.x * 128;

    // gmem->smem loader mapping: 2 threads per 64B row (K-tile 32 bf16)
    const int r = tid >> 1, h = tid & 1;

    // ldmatrix per-lane offsets
    const int lr = lid & 7, grp = lid >> 3;
    const int a_ro = (grp & 1) * 8 + lr, a_co = (grp >> 1) * 8;  // A: m-rows, k-cols
    const int b_ro = (grp >> 1) * 8 + lr, b_co = (grp & 1) * 8;  // B: n-rows, k-cols

    const uint32_t sA = smem_u32(As), sB = smem_u32(Bs);

    float acc[4][4][4];
#pragma unroll
    for (int i = 0; i < 4; i++)
#pragma unroll
        for (int j = 0; j < 4; j++)
#pragma unroll
            for (int q = 0; q < 4; q++) acc[i][j][q] = 0.0f;

    const __nv_bfloat16* Aph[3] = {A0, A1, A2};
    const __nv_bfloat16* Bph[3] = {B0, B1, B2};
    const int kcs[3] = {kc0, kc1, kc2};

    for (int p = 0; p < 3; p++) {
        const int kc = kcs[p];
        if (kc == 0) continue;
        const __nv_bfloat16* Ap = Aph[p];
        const __nv_bfloat16* Bp = Bph[p];
        const size_t stride = (size_t)kc * 64;
        const int ntile = kc * 2;                    // K-tiles of 32

        auto gload = [&](int kt, uint4 va[2], uint4 vb[2]) {
            const size_t koff = (size_t)kt * 32 + (size_t)h * 16;
            const uint4* pa = (const uint4*)(Ap + (size_t)(m0 + r) * stride + koff);
            va[0] = pa[0]; va[1] = pa[1];
            const uint4* pb = (const uint4*)(Bp + (size_t)(n0 + r) * stride + koff);
            vb[0] = pb[0]; vb[1] = pb[1];
        };
        auto sstore = [&](int st, uint4 va[2], uint4 vb[2]) {
            __nv_bfloat16* da = &As[st][r * LDA + h * 16];
            *(uint4*)da = va[0]; *(uint4*)(da + 8) = va[1];
            __nv_bfloat16* db = &Bs[st][r * LDA + h * 16];
            *(uint4*)db = vb[0]; *(uint4*)(db + 8) = vb[1];
        };

        { uint4 va[2], vb[2]; gload(0, va, vb); sstore(0, va, vb); }
        __syncthreads();

        for (int kt = 0; kt < ntile; kt++) {
            const int st = kt & 1;
            const bool more = (kt + 1 < ntile);
            uint4 va[2], vb[2];
            if (more) gload(kt + 1, va, vb);

            const uint32_t baseA = sA + (uint32_t)st * 128 * LDA * 2;
            const uint32_t baseB = sB + (uint32_t)st * 128 * LDA * 2;
#pragma unroll
            for (int kk = 0; kk < 2; kk++) {
                uint32_t af[4][4], bf_[2][4];
#pragma unroll
                for (int mt = 0; mt < 4; mt++) {
                    const uint32_t ad = baseA +
                        (uint32_t)((wm * 64 + mt * 16 + a_ro) * LDA + kk * 16 + a_co) * 2;
                    LDMX4(af[mt], ad);
                }
#pragma unroll
                for (int nt = 0; nt < 2; nt++) {
                    const uint32_t bd = baseB +
                        (uint32_t)((wn * 32 + nt * 16 + b_ro) * LDA + kk * 16 + b_co) * 2;
                    LDMX4(bf_[nt], bd);
                }
#pragma unroll
                for (int mt = 0; mt < 4; mt++)
#pragma unroll
                    for (int nb = 0; nb < 4; nb++)
                        MMA16816(acc[mt][nb], af[mt],
                                 bf_[nb >> 1][(nb & 1) * 2], bf_[nb >> 1][(nb & 1) * 2 + 1]);
            }

            if (more) sstore(st ^ 1, va, vb);
            __syncthreads();
        }
    }

    // ---- epilogue: c-fragment (m16n8): rows t/4, t/4+8; cols 2*(t%4)+{0,1} ----
    const int er = lid >> 2, ec = (lid & 3) * 2;
#pragma unroll
    for (int mt = 0; mt < 4; mt++) {
#pragma unroll
        for (int nb = 0; nb < 4; nb++) {
            const int row = m0 + wm * 64 + mt * 16 + er;
            const int col = n0 + wn * 32 + nb * 8 + ec;
#pragma unroll
            for (int half = 0; half < 2; half++) {
                const size_t o = (size_t)(row + half * 8) * NN_ + col;
                float v0 = acc[mt][nb][half * 2 + 0];
                float v1 = acc[mt][nb][half * 2 + 1];
                if (EPI == 0) {
                    v0 *= Smask[o]; v1 *= Smask[o + 1];
                    __nv_bfloat162 hv;
                    hv.x = __float2bfloat16(v0); hv.y = __float2bfloat16(v1);
                    *(__nv_bfloat162*)&outH[o] = hv;
                } else {
                    float2 fv; fv.x = v0; fv.y = v1;
                    *(float2*)&outF[o] = fv;
                }
            }
        }
    }
}

// ---------------------------------------------------------------------------
// fp32 SGEMM (GEMM-1 only): C = A @ B_stored^T + bias (NT), packed f32x2 FMA
// ---------------------------------------------------------------------------
__device__ __forceinline__ unsigned long long bcast2(float a) {
    unsigned long long r; asm("mov.b64 %0, {%1, %1};" : "=l"(r) : "f"(a)); return r;
}
__device__ __forceinline__ void ffma2(unsigned long long& d, unsigned long long a, unsigned long long b) {
    asm("fma.rn.f32x2 %0, %1, %2, %0;" : "+l"(d) : "l"(a), "l"(b));
}
__device__ __forceinline__ float2 unpack2(unsigned long long v) {
    float2 r; asm("mov.b64 {%0, %1}, %2;" : "=f"(r.x), "=f"(r.y) : "l"(v)); return r;
}

__global__ __launch_bounds__(256)
void sgemm_nt_bias(const float* __restrict__ A, const float* __restrict__ B,
                   float* __restrict__ C, int M, int N, int K,
                   const float* __restrict__ bias)
{
    __shared__ float As[2][8][128];
    __shared__ float Bs[2][8][128];
    const int tid = threadIdx.x;
    const int row0 = blockIdx.y * 128, col0 = blockIdx.x * 128;
    const int ty = tid >> 4, tx = tid & 15;

    unsigned long long acc2[8][4];
#pragma unroll
    for (int i = 0; i < 8; i++)
#pragma unroll
        for (int j = 0; j < 4; j++) acc2[i][j] = 0ull;

    auto ldA = [&](int k0) -> float4 {
        const int rr = tid >> 1, kq = (tid & 1) << 2;
        return *reinterpret_cast<const float4*>(&A[(size_t)(row0 + rr) * K + (k0 + kq)]);
    };
    auto stA = [&](int buf, float4 v) {
        const int rr = tid >> 1, kq = (tid & 1) << 2;
        As[buf][kq+0][rr]=v.x; As[buf][kq+1][rr]=v.y; As[buf][kq+2][rr]=v.z; As[buf][kq+3][rr]=v.w;
    };
    auto ldB = [&](int k0) -> float4 {
        const int cc = tid >> 1, kq = (tid & 1) << 2;
        return *reinterpret_cast<const float4*>(&B[(size_t)(col0 + cc) * K + (k0 + kq)]);
    };
    auto stB = [&](int buf, float4 v) {
        const int cc = tid >> 1, kq = (tid & 1) << 2;
        Bs[buf][kq+0][cc]=v.x; Bs[buf][kq+1][cc]=v.y; Bs[buf][kq+2][cc]=v.z; Bs[buf][kq+3][cc]=v.w;
    };

    { float4 va = ldA(0), vb = ldB(0); stA(0, va); stB(0, vb); }
    __syncthreads();
    const int nk = K >> 3;
    for (int kt = 0; kt < nk; kt++) {
        const int buf = kt & 1;
        const bool more = (kt + 1 < nk);
        float4 va, vb;
        if (more) { va = ldA((kt + 1) << 3); vb = ldB((kt + 1) << 3); }
#pragma unroll
        for (int kk = 0; kk < 8; kk++) {
            const float4 a0 = *reinterpret_cast<const float4*>(&As[buf][kk][ty*8+0]);
            const float4 a1 = *reinterpret_cast<const float4*>(&As[buf][kk][ty*8+4]);
            const double2 b01 = *reinterpret_cast<const double2*>(&Bs[buf][kk][tx*8+0]);
            const double2 b23 = *reinterpret_cast<const double2*>(&Bs[buf][kk][tx*8+4]);
            const unsigned long long bp0 = __double_as_longlong(b01.x);
            const unsigned long long bp1 = __double_as_longlong(b01.y);
            const unsigned long long bp2 = __double_as_longlong(b23.x);
            const unsigned long long bp3 = __double_as_longlong(b23.y);
            const float av[8] = {a0.x,a0.y,a0.z,a0.w,a1.x,a1.y,a1.z,a1.w};
#pragma unroll
            for (int i = 0; i < 8; i++) {
                const unsigned long long ap = bcast2(av[i]);
                ffma2(acc2[i][0], ap, bp0); ffma2(acc2[i][1], ap, bp1);
                ffma2(acc2[i][2], ap, bp2); ffma2(acc2[i][3], ap, bp3);
            }
        }
        if (more) { stA(buf ^ 1, va); stB(buf ^ 1, vb); }
        __syncthreads();
    }
#pragma unroll
    for (int i = 0; i < 8; i++) {
        const int row = row0 + ty * 8 + i;
#pragma unroll
        for (int jp = 0; jp < 4; jp++) {
            float2 v = unpack2(acc2[i][jp]);
            const int col = col0 + tx * 8 + jp * 2;
            v.x += bias[col]; v.y += bias[col + 1];
            *reinterpret_cast<float2*>(&C[(size_t)row * N + col]) = v;
        }
    }
}

// ---------------------------------------------------------------------------
// Helper passes
// ---------------------------------------------------------------------------
// out[c][r] = bf16(in[r][c]) (+lo part if SPLIT)
template<bool SPLIT>
__global__ __launch_bounds__(256)
void transpose_cvt(const float* __restrict__ in, __nv_bfloat16* __restrict__ oh,
                   __nv_bfloat16* __restrict__ ol, int R, int C)
{
    __shared__ float t[32][33];
    const int rb = blockIdx.y * 32, cb = blockIdx.x * 32;
    const int tx = threadIdx.x, ty = threadIdx.y;
#pragma unroll
    for (int rr = 0; rr < 32; rr += 8)
        t[ty + rr][tx] = in[(size_t)(rb + ty + rr) * C + (cb + tx)];
    __syncthreads();
#pragma unroll
    for (int rr = 0; rr < 32; rr += 8) {
        const float v = t[tx][ty + rr];
        const size_t o = (size_t)(cb + ty + rr) * R + (rb + tx);
        const __nv_bfloat16 hh = __float2bfloat16(v);
        oh[o] = hh;
        if (SPLIT) ol[o] = __float2bfloat16(v - __bfloat162float(hh));
    }
}

__global__ __launch_bounds__(256)
void transpose_bf16(const __nv_bfloat16* __restrict__ in, __nv_bfloat16* __restrict__ out, int R, int C)
{
    __shared__ __nv_bfloat16 t[32][33];
    const int rb = blockIdx.y * 32, cb = blockIdx.x * 32;
    const int tx = threadIdx.x, ty = threadIdx.y;
#pragma unroll
    for (int rr = 0; rr < 32; rr += 8)
        t[ty + rr][tx] = in[(size_t)(rb + ty + rr) * C + (cb + tx)];
    __syncthreads();
#pragma unroll
    for (int rr = 0; rr < 32; rr += 8)
        out[(size_t)(cb + ty + rr) * R + (rb + tx)] = t[tx][ty + rr];
}

__global__ __launch_bounds__(256)
void split_cvt(const float* __restrict__ in, __nv_bfloat16* __restrict__ oh,
               __nv_bfloat16* __restrict__ ol, size_t n)
{
    const size_t i = (size_t)blockIdx.x * 256 + threadIdx.x;
    if (i < n) {
        const float v = in[i];
        const __nv_bfloat16 hh = __float2bfloat16(v);
        oh[i] = hh;
        ol[i] = __float2bfloat16(v - __bfloat162float(hh));
    }
}

// out[k][j] = wf[j][k] * PW[j][k] / nc[k]^2   (transposed elementwise)
__global__ __launch_bounds__(256)
void finalize_kernel(const float* __restrict__ wf, const float* __restrict__ PW,
                     const float* __restrict__ nc, float* __restrict__ out)
{
    __shared__ float t[32][33];
    const int kb = blockIdx.x * 32;
    const int jb = blockIdx.y * 32;
    const int tx = threadIdx.x, ty = threadIdx.y;
#pragma unroll
    for (int rr = 0; rr < 32; rr += 8) {
        const size_t idx = (size_t)(jb + ty + rr) * NN_ + (kb + tx);
        t[ty + rr][tx] = wf[idx] * PW[idx];
    }
    __syncthreads();
#pragma unroll
    for (int rr = 0; rr < 32; rr += 8) {
        const int k = kb + ty + rr;
        const float n = nc[k];
        const float inv = 1.0f / (n * n);
        out[(size_t)k * NN_ + (jb + tx)] = t[tx][ty + rr] * inv;
    }
}

// ---------------------------------------------------------------------------
extern "C" void kernel_launch(void* const* d_in, const int* in_sizes, int n_in,
                              void* d_out, int out_size)
{
    const float* nf  = (const float*)d_in[0];  // (4096, 512)
    const float* adj = (const float*)d_in[1];  // (4096, 4096)
    const float* nc  = (const float*)d_in[3];  // (4096, 1)
    const float* S   = (const float*)d_in[4];  // mask_hadamard == S (4096, 4096)
    const float* lw  = (const float*)d_in[5];  // (1024, 512)
    const float* lb  = (const float*)d_in[6];  // (1024,)
    const float* w   = (const float*)d_in[7];  // (1024, 4096)
    float* out = (float*)d_out;

    float *x, *wf, *PW;
    __nv_bfloat16 *xh, *xl, *At, *Wth, *Wtl, *wfTh, *wfTl, *Q, *Prm;
    cudaGetSymbolAddress((void**)&x,    g_x);
    cudaGetSymbolAddress((void**)&xh,   g_xh);
    cudaGetSymbolAddress((void**)&xl,   g_xl);
    cudaGetSymbolAddress((void**)&At,   g_At);
    cudaGetSymbolAddress((void**)&Wth,  g_Wth);
    cudaGetSymbolAddress((void**)&Wtl,  g_Wtl);
    cudaGetSymbolAddress((void**)&wf,   g_wf);
    cudaGetSymbolAddress((void**)&wfTh, g_wfTh);
    cudaGetSymbolAddress((void**)&wfTl, g_wfTl);
    cudaGetSymbolAddress((void**)&Q,    g_Q);
    cudaGetSymbolAddress((void**)&Prm,  g_Prm);
    cudaGetSymbolAddress((void**)&PW,   g_PW);

    // 1) x = NF @ lw^T + b   (fp32, exact)
    sgemm_nt_bias<<<dim3(INF/128, NN_/128), 256>>>(nf, lw, x, NN_, INF, FRAW, lb);

    // 2) operand prep
    split_cvt<<<(unsigned)(((size_t)NN_*INF + 255)/256), 256>>>(x, xh, xl, (size_t)NN_*INF);
    transpose_cvt<false><<<dim3(NN_/32, NN_/32), dim3(32, 8)>>>(adj, At, nullptr, NN_, NN_);
    transpose_cvt<true ><<<dim3(OUTF/32, INF/32), dim3(32, 8)>>>(w, Wth, Wtl, INF, OUTF);

    // 3) GEMM-2 (HMMA, 3-term split): wf = xh@Wth^T + xh@Wtl^T + xl@Wth^T  (row-major fp32)
    tensor_gemm<1><<<dim3(OUTF/128, NN_/128), 256>>>(
        xh, Wth, INF/64,  xh, Wtl, INF/64,  xl, Wth, INF/64,
        wf, nullptr, nullptr);

    // 4) wf^T hi/lo split for GEMM-4's B operand
    transpose_cvt<true><<<dim3(OUTF/32, NN_/32), dim3(32, 8)>>>(wf, wfTh, wfTl, NN_, OUTF);

    // 5) GEMM-3 (HMMA, exact): Q[i][j] = (A^T A)[i][j] * S[i][j]  (aligned mask; Q = P^T)
    tensor_gemm<0><<<dim3(NN_/128, NN_/128), 256>>>(
        At, At, NN_/64,  nullptr, nullptr, 0,  nullptr, nullptr, 0,
        nullptr, Q, S);

    // 6) P row-major = Q^T
    transpose_bf16<<<dim3(NN_/32, NN_/32), dim3(32, 8)>>>(Q, Prm, NN_, NN_);

    // 7) GEMM-4 (HMMA, wf split): PW = P@wfh + P@wfl  (row-major fp32)
    tensor_gemm<1><<<dim3(OUTF/128, NN_/128), 256>>>(
        Prm, wfTh, NN_/64,  Prm, wfTl, NN_/64,  nullptr, nullptr, 0,
        PW, nullptr, nullptr);

    // 8) out[k][j] = wf[j][k]*PW[j][k]/nc[k]^2
    finalize_kernel<<<dim3(NN_/32, NN_/32), dim3(32, 8)>>>(wf, PW, nc, out);
}

// round 12
// speedup vs baseline: 4.5073x; 1.0264x over previous
#include <cuda_runtime.h>
#include <cuda_bf16.h>
#include <cstddef>
#include <cstdint>

// Problem constants
#define NN_ 4096
#define FRAW 512
#define INF 1024
#define OUTF 4096

// ---------------------------------------------------------------------------
// Scratch (device globals — no allocation allowed)
// ---------------------------------------------------------------------------
__device__ float         g_x   [(size_t)NN_ * INF];     // 16 MB
__device__ __nv_bfloat16 g_xh  [(size_t)NN_ * INF];     // 8 MB
__device__ __nv_bfloat16 g_xl  [(size_t)NN_ * INF];     // 8 MB
__device__ __nv_bfloat16 g_At  [(size_t)NN_ * NN_];     // 32 MB  A^T bf16
__device__ __nv_bfloat16 g_Wth [(size_t)OUTF * INF];    // 8 MB   W^T hi
__device__ __nv_bfloat16 g_Wtl [(size_t)OUTF * INF];    // 8 MB   W^T lo
__device__ float         g_wf  [(size_t)NN_ * OUTF];    // 64 MB  wf fp32 row-major
__device__ __nv_bfloat16 g_wfTh[(size_t)OUTF * NN_];    // 32 MB  wf^T hi
__device__ __nv_bfloat16 g_wfTl[(size_t)OUTF * NN_];    // 32 MB  wf^T lo
__device__ __nv_bfloat16 g_Q   [(size_t)NN_ * NN_];     // 32 MB  Q = G.*S (row-major) = P^T
__device__ __nv_bfloat16 g_Prm [(size_t)NN_ * NN_];     // 32 MB  P row-major bf16
__device__ float         g_PW  [(size_t)NN_ * OUTF];    // 64 MB  P@wf fp32 row-major

// ---------------------------------------------------------------------------
// mma.sync / ldmatrix / cp.async helpers (sm_80+ — valid for compute_103 PTX)
// ---------------------------------------------------------------------------
__device__ __forceinline__ uint32_t smem_u32(const void* p) {
    uint32_t a;
    asm("{ .reg .u64 t; cvta.to.shared.u64 t, %1; cvt.u32.u64 %0, t; }" : "=r"(a) : "l"(p));
    return a;
}

#define LDMX4(rr, addr) \
    asm volatile("ldmatrix.sync.aligned.m8n8.x4.shared.b16 {%0,%1,%2,%3}, [%4];" \
        : "=r"((rr)[0]), "=r"((rr)[1]), "=r"((rr)[2]), "=r"((rr)[3]) : "r"(addr))

#define MMA16816(c, a, b0, b1) \
    asm volatile("mma.sync.aligned.m16n8k16.row.col.f32.bf16.bf16.f32 " \
        "{%0,%1,%2,%3}, {%4,%5,%6,%7}, {%8,%9}, {%0,%1,%2,%3};" \
        : "+f"((c)[0]), "+f"((c)[1]), "+f"((c)[2]), "+f"((c)[3]) \
        : "r"((a)[0]), "r"((a)[1]), "r"((a)[2]), "r"((a)[3]), "r"(b0), "r"(b1))

__device__ __forceinline__ void cp16(uint32_t d, const void* g) {
    asm volatile("cp.async.cg.shared.global [%0], [%1], 16;"
        :: "r"(d), "l"(__cvta_generic_to_global(g)));
}
#define CP_COMMIT() asm volatile("cp.async.commit_group;")
#define CP_WAIT2()  asm volatile("cp.async.wait_group 2;")

// ---------------------------------------------------------------------------
// Tensor GEMM (HMMA): C[M,N] tile 128x128 = sum over up to 3 phases of Ap @ Bp^T
//   Ap row-major [M, kcP*64] bf16; Bp row-major [N, kcP*64] bf16 (NT form)
//   EPI 0: outH[m*NN_+n] = bf16(C * Smask[m*NN_+n])   (GEMM-3: Q = G.*S, aligned)
//   EPI 1: outF[m*NN_+n] = C                          (GEMM-2 / GEMM-4)
// 256 threads = 8 warps (2 x 4), warp tile 64x32, K-tile 32.
// 4-stage cp.async ring, 3-deep prefetch (hides ~577-cyc DRAM latency).
// ---------------------------------------------------------------------------
#define LDA 40                     // padded row (bf16) — conflict-free ldmatrix
#define STAGES 4
#define STAGE_B (128 * LDA * 2)    // 10240 B per operand per stage
#define DSM_BYTES (2 * STAGES * STAGE_B)   // 81920 B dynamic smem

template<int EPI>
__global__ __launch_bounds__(256, 1)
void tensor_gemm(const __nv_bfloat16* __restrict__ A0, const __nv_bfloat16* __restrict__ B0, int kc0,
                 const __nv_bfloat16* __restrict__ A1, const __nv_bfloat16* __restrict__ B1, int kc1,
                 const __nv_bfloat16* __restrict__ A2, const __nv_bfloat16* __restrict__ B2, int kc2,
                 float* __restrict__ outF, __nv_bfloat16* __restrict__ outH,
                 const float* __restrict__ Smask)
{
    extern __shared__ char dsm[];
    const uint32_t sA = smem_u32(dsm);
    const uint32_t sB = sA + STAGES * STAGE_B;

    const int tid = threadIdx.x;
    const int lid = tid & 31, wid = tid >> 5;
    const int wm = wid >> 2, wn = wid & 3;          // warp grid 2 x 4
    const int m0 = blockIdx.y * 128, n0 = blockIdx.x * 128;

    // gmem->smem loader mapping: 2 threads per row, each moves 32B per operand
    const int r = tid >> 1, h = tid & 1;

    // ldmatrix per-lane offsets
    const int lr = lid & 7, grp = lid >> 3;
    const int a_ro = (grp & 1) * 8 + lr, a_co = (grp >> 1) * 8;  // A: m-rows, k-cols
    const int b_ro = (grp >> 1) * 8 + lr, b_co = (grp & 1) * 8;  // B: n-rows, k-cols

    float acc[4][4][4];
#pragma unroll
    for (int i = 0; i < 4; i++)
#pragma unroll
        for (int j = 0; j < 4; j++)
#pragma unroll
            for (int q = 0; q < 4; q++) acc[i][j][q] = 0.0f;

    const int T2 = 2 * (kc0 + kc1 + kc2);           // total K-tiles of 32

    // Issue async loads for global K-tile t into ring stage t%4. Always commits
    // a group (possibly empty) so wait_group counting stays uniform.
    auto issue = [&](int t) {
        if (t < T2) {
            const __nv_bfloat16 *Ap, *Bp; size_t stride; int tl;
            if (t < 2 * kc0)              { Ap = A0; Bp = B0; stride = (size_t)kc0 * 64; tl = t; }
            else if (t < 2 * (kc0 + kc1)) { Ap = A1; Bp = B1; stride = (size_t)kc1 * 64; tl = t - 2 * kc0; }
            else                          { Ap = A2; Bp = B2; stride = (size_t)kc2 * 64; tl = t - 2 * (kc0 + kc1); }
            const int st = t & (STAGES - 1);
            const size_t koff = (size_t)tl * 32 + (size_t)h * 16;
            const __nv_bfloat16* ga = Ap + (size_t)(m0 + r) * stride + koff;
            const __nv_bfloat16* gb = Bp + (size_t)(n0 + r) * stride + koff;
            const uint32_t da = sA + st * STAGE_B + (uint32_t)(r * LDA + h * 16) * 2;
            const uint32_t db = sB + st * STAGE_B + (uint32_t)(r * LDA + h * 16) * 2;
            cp16(da, ga); cp16(da + 16, ga + 8);
            cp16(db, gb); cp16(db + 16, gb + 8);
        }
        CP_COMMIT();
    };

    issue(0); issue(1); issue(2);                   // prologue: 3 stages in flight

    for (int kt = 0; kt < T2; kt++) {
        CP_WAIT2();            // stage kt complete (<=2 newer groups pending)
        __syncthreads();       // writes visible; all readers of stage kt-1 done
        issue(kt + 3);         // overwrites stage (kt-1)%4 — safe after the sync

        const int st = kt & (STAGES - 1);
        const uint32_t baseA = sA + (uint32_t)st * STAGE_B;
        const uint32_t baseB = sB + (uint32_t)st * STAGE_B;
#pragma unroll
        for (int kk = 0; kk < 2; kk++) {
            uint32_t af[4][4], bf_[2][4];
#pragma unroll
            for (int mt = 0; mt < 4; mt++) {
                const uint32_t ad = baseA +
                    (uint32_t)((wm * 64 + mt * 16 + a_ro) * LDA + kk * 16 + a_co) * 2;
                LDMX4(af[mt], ad);
            }
#pragma unroll
            for (int nt = 0; nt < 2; nt++) {
                const uint32_t bd = baseB +
                    (uint32_t)((wn * 32 + nt * 16 + b_ro) * LDA + kk * 16 + b_co) * 2;
                LDMX4(bf_[nt], bd);
            }
#pragma unroll
            for (int mt = 0; mt < 4; mt++)
#pragma unroll
                for (int nb = 0; nb < 4; nb++)
                    MMA16816(acc[mt][nb], af[mt],
                             bf_[nb >> 1][(nb & 1) * 2], bf_[nb >> 1][(nb & 1) * 2 + 1]);
        }
    }

    // ---- epilogue: c-fragment (m16n8): rows t/4, t/4+8; cols 2*(t%4)+{0,1} ----
    const int er = lid >> 2, ec = (lid & 3) * 2;
#pragma unroll
    for (int mt = 0; mt < 4; mt++) {
#pragma unroll
        for (int nb = 0; nb < 4; nb++) {
            const int row = m0 + wm * 64 + mt * 16 + er;
            const int col = n0 + wn * 32 + nb * 8 + ec;
#pragma unroll
            for (int half = 0; half < 2; half++) {
                const size_t o = (size_t)(row + half * 8) * NN_ + col;
                float v0 = acc[mt][nb][half * 2 + 0];
                float v1 = acc[mt][nb][half * 2 + 1];
                if (EPI == 0) {
                    v0 *= Smask[o]; v1 *= Smask[o + 1];
                    __nv_bfloat162 hv;
                    hv.x = __float2bfloat16(v0); hv.y = __float2bfloat16(v1);
                    *(__nv_bfloat162*)&outH[o] = hv;
                } else {
                    float2 fv; fv.x = v0; fv.y = v1;
                    *(float2*)&outF[o] = fv;
                }
            }
        }
    }
}

// ---------------------------------------------------------------------------
// fp32 SGEMM (GEMM-1 only): C = A @ B_stored^T + bias (NT), packed f32x2 FMA
// ---------------------------------------------------------------------------
__device__ __forceinline__ unsigned long long bcast2(float a) {
    unsigned long long r; asm("mov.b64 %0, {%1, %1};" : "=l"(r) : "f"(a)); return r;
}
__device__ __forceinline__ void ffma2(unsigned long long& d, unsigned long long a, unsigned long long b) {
    asm("fma.rn.f32x2 %0, %1, %2, %0;" : "+l"(d) : "l"(a), "l"(b));
}
__device__ __forceinline__ float2 unpack2(unsigned long long v) {
    float2 r; asm("mov.b64 {%0, %1}, %2;" : "=f"(r.x), "=f"(r.y) : "l"(v)); return r;
}

__global__ __launch_bounds__(256)
void sgemm_nt_bias(const float* __restrict__ A, const float* __restrict__ B,
                   float* __restrict__ C, int M, int N, int K,
                   const float* __restrict__ bias)
{
    __shared__ float As[2][8][128];
    __shared__ float Bs[2][8][128];
    const int tid = threadIdx.x;
    const int row0 = blockIdx.y * 128, col0 = blockIdx.x * 128;
    const int ty = tid >> 4, tx = tid & 15;

    unsigned long long acc2[8][4];
#pragma unroll
    for (int i = 0; i < 8; i++)
#pragma unroll
        for (int j = 0; j < 4; j++) acc2[i][j] = 0ull;

    auto ldA = [&](int k0) -> float4 {
        const int rr = tid >> 1, kq = (tid & 1) << 2;
        return *reinterpret_cast<const float4*>(&A[(size_t)(row0 + rr) * K + (k0 + kq)]);
    };
    auto stA = [&](int buf, float4 v) {
        const int rr = tid >> 1, kq = (tid & 1) << 2;
        As[buf][kq+0][rr]=v.x; As[buf][kq+1][rr]=v.y; As[buf][kq+2][rr]=v.z; As[buf][kq+3][rr]=v.w;
    };
    auto ldB = [&](int k0) -> float4 {
        const int cc = tid >> 1, kq = (tid & 1) << 2;
        return *reinterpret_cast<const float4*>(&B[(size_t)(col0 + cc) * K + (k0 + kq)]);
    };
    auto stB = [&](int buf, float4 v) {
        const int cc = tid >> 1, kq = (tid & 1) << 2;
        Bs[buf][kq+0][cc]=v.x; Bs[buf][kq+1][cc]=v.y; Bs[buf][kq+2][cc]=v.z; Bs[buf][kq+3][cc]=v.w;
    };

    { float4 va = ldA(0), vb = ldB(0); stA(0, va); stB(0, vb); }
    __syncthreads();
    const int nk = K >> 3;
    for (int kt = 0; kt < nk; kt++) {
        const int buf = kt & 1;
        const bool more = (kt + 1 < nk);
        float4 va, vb;
        if (more) { va = ldA((kt + 1) << 3); vb = ldB((kt + 1) << 3); }
#pragma unroll
        for (int kk = 0; kk < 8; kk++) {
            const float4 a0 = *reinterpret_cast<const float4*>(&As[buf][kk][ty*8+0]);
            const float4 a1 = *reinterpret_cast<const float4*>(&As[buf][kk][ty*8+4]);
            const double2 b01 = *reinterpret_cast<const double2*>(&Bs[buf][kk][tx*8+0]);
            const double2 b23 = *reinterpret_cast<const double2*>(&Bs[buf][kk][tx*8+4]);
            const unsigned long long bp0 = __double_as_longlong(b01.x);
            const unsigned long long bp1 = __double_as_longlong(b01.y);
            const unsigned long long bp2 = __double_as_longlong(b23.x);
            const unsigned long long bp3 = __double_as_longlong(b23.y);
            const float av[8] = {a0.x,a0.y,a0.z,a0.w,a1.x,a1.y,a1.z,a1.w};
#pragma unroll
            for (int i = 0; i < 8; i++) {
                const unsigned long long ap = bcast2(av[i]);
                ffma2(acc2[i][0], ap, bp0); ffma2(acc2[i][1], ap, bp1);
                ffma2(acc2[i][2], ap, bp2); ffma2(acc2[i][3], ap, bp3);
            }
        }
        if (more) { stA(buf ^ 1, va); stB(buf ^ 1, vb); }
        __syncthreads();
    }
#pragma unroll
    for (int i = 0; i < 8; i++) {
        const int row = row0 + ty * 8 + i;
#pragma unroll
        for (int jp = 0; jp < 4; jp++) {
            float2 v = unpack2(acc2[i][jp]);
            const int col = col0 + tx * 8 + jp * 2;
            v.x += bias[col]; v.y += bias[col + 1];
            *reinterpret_cast<float2*>(&C[(size_t)row * N + col]) = v;
        }
    }
}

// ---------------------------------------------------------------------------
// Helper passes
// ---------------------------------------------------------------------------
// out[c][r] = bf16(in[r][c]) (+lo part if SPLIT)
template<bool SPLIT>
__global__ __launch_bounds__(256)
void transpose_cvt(const float* __restrict__ in, __nv_bfloat16* __restrict__ oh,
                   __nv_bfloat16* __restrict__ ol, int R, int C)
{
    __shared__ float t[32][33];
    const int rb = blockIdx.y * 32, cb = blockIdx.x * 32;
    const int tx = threadIdx.x, ty = threadIdx.y;
#pragma unroll
    for (int rr = 0; rr < 32; rr += 8)
        t[ty + rr][tx] = in[(size_t)(rb + ty + rr) * C + (cb + tx)];
    __syncthreads();
#pragma unroll
    for (int rr = 0; rr < 32; rr += 8) {
        const float v = t[tx][ty + rr];
        const size_t o = (size_t)(cb + ty + rr) * R + (rb + tx);
        const __nv_bfloat16 hh = __float2bfloat16(v);
        oh[o] = hh;
        if (SPLIT) ol[o] = __float2bfloat16(v - __bfloat162float(hh));
    }
}

__global__ __launch_bounds__(256)
void transpose_bf16(const __nv_bfloat16* __restrict__ in, __nv_bfloat16* __restrict__ out, int R, int C)
{
    __shared__ __nv_bfloat16 t[32][33];
    const int rb = blockIdx.y * 32, cb = blockIdx.x * 32;
    const int tx = threadIdx.x, ty = threadIdx.y;
#pragma unroll
    for (int rr = 0; rr < 32; rr += 8)
        t[ty + rr][tx] = in[(size_t)(rb + ty + rr) * C + (cb + tx)];
    __syncthreads();
#pragma unroll
    for (int rr = 0; rr < 32; rr += 8)
        out[(size_t)(cb + ty + rr) * R + (rb + tx)] = t[tx][ty + rr];
}

__global__ __launch_bounds__(256)
void split_cvt(const float* __restrict__ in, __nv_bfloat16* __restrict__ oh,
               __nv_bfloat16* __restrict__ ol, size_t n)
{
    const size_t i = (size_t)blockIdx.x * 256 + threadIdx.x;
    if (i < n) {
        const float v = in[i];
        const __nv_bfloat16 hh = __float2bfloat16(v);
        oh[i] = hh;
        ol[i] = __float2bfloat16(v - __bfloat162float(hh));
    }
}

// out[k][j] = wf[j][k] * PW[j][k] / nc[k]^2   (transposed elementwise)
__global__ __launch_bounds__(256)
void finalize_kernel(const float* __restrict__ wf, const float* __restrict__ PW,
                     const float* __restrict__ nc, float* __restrict__ out)
{
    __shared__ float t[32][33];
    const int kb = blockIdx.x * 32;
    const int jb = blockIdx.y * 32;
    const int tx = threadIdx.x, ty = threadIdx.y;
#pragma unroll
    for (int rr = 0; rr < 32; rr += 8) {
        const size_t idx = (size_t)(jb + ty + rr) * NN_ + (kb + tx);
        t[ty + rr][tx] = wf[idx] * PW[idx];
    }
    __syncthreads();
#pragma unroll
    for (int rr = 0; rr < 32; rr += 8) {
        const int k = kb + ty + rr;
        const float n = nc[k];
        const float inv = 1.0f / (n * n);
        out[(size_t)k * NN_ + (jb + tx)] = t[tx][ty + rr] * inv;
    }
}

// ---------------------------------------------------------------------------
extern "C" void kernel_launch(void* const* d_in, const int* in_sizes, int n_in,
                              void* d_out, int out_size)
{
    const float* nf  = (const float*)d_in[0];  // (4096, 512)
    const float* adj = (const float*)d_in[1];  // (4096, 4096)
    const float* nc  = (const float*)d_in[3];  // (4096, 1)
    const float* S   = (const float*)d_in[4];  // mask_hadamard == S (4096, 4096)
    const float* lw  = (const float*)d_in[5];  // (1024, 512)
    const float* lb  = (const float*)d_in[6];  // (1024,)
    const float* w   = (const float*)d_in[7];  // (1024, 4096)
    float* out = (float*)d_out;

    float *x, *wf, *PW;
    __nv_bfloat16 *xh, *xl, *At, *Wth, *Wtl, *wfTh, *wfTl, *Q, *Prm;
    cudaGetSymbolAddress((void**)&x,    g_x);
    cudaGetSymbolAddress((void**)&xh,   g_xh);
    cudaGetSymbolAddress((void**)&xl,   g_xl);
    cudaGetSymbolAddress((void**)&At,   g_At);
    cudaGetSymbolAddress((void**)&Wth,  g_Wth);
    cudaGetSymbolAddress((void**)&Wtl,  g_Wtl);
    cudaGetSymbolAddress((void**)&wf,   g_wf);
    cudaGetSymbolAddress((void**)&wfTh, g_wfTh);
    cudaGetSymbolAddress((void**)&wfTl, g_wfTl);
    cudaGetSymbolAddress((void**)&Q,    g_Q);
    cudaGetSymbolAddress((void**)&Prm,  g_Prm);
    cudaGetSymbolAddress((void**)&PW,   g_PW);

    cudaFuncSetAttribute(tensor_gemm<0>, cudaFuncAttributeMaxDynamicSharedMemorySize, DSM_BYTES);
    cudaFuncSetAttribute(tensor_gemm<1>, cudaFuncAttributeMaxDynamicSharedMemorySize, DSM_BYTES);

    // 1) x = NF @ lw^T + b   (fp32, exact)
    sgemm_nt_bias<<<dim3(INF/128, NN_/128), 256>>>(nf, lw, x, NN_, INF, FRAW, lb);

    // 2) operand prep
    split_cvt<<<(unsigned)(((size_t)NN_*INF + 255)/256), 256>>>(x, xh, xl, (size_t)NN_*INF);
    transpose_cvt<false><<<dim3(NN_/32, NN_/32), dim3(32, 8)>>>(adj, At, nullptr, NN_, NN_);
    transpose_cvt<true ><<<dim3(OUTF/32, INF/32), dim3(32, 8)>>>(w, Wth, Wtl, INF, OUTF);

    // 3) GEMM-2 (HMMA, 3-term split): wf = xh@Wth^T + xh@Wtl^T + xl@Wth^T  (row-major fp32)
    tensor_gemm<1><<<dim3(OUTF/128, NN_/128), 256, DSM_BYTES>>>(
        xh, Wth, INF/64,  xh, Wtl, INF/64,  xl, Wth, INF/64,
        wf, nullptr, nullptr);

    // 4) wf^T hi/lo split for GEMM-4's B operand
    transpose_cvt<true><<<dim3(OUTF/32, NN_/32), dim3(32, 8)>>>(wf, wfTh, wfTl, NN_, OUTF);

    // 5) GEMM-3 (HMMA, exact): Q[i][j] = (A^T A)[i][j] * S[i][j]  (aligned mask; Q = P^T)
    tensor_gemm<0><<<dim3(NN_/128, NN_/128), 256, DSM_BYTES>>>(
        At, At, NN_/64,  nullptr, nullptr, 0,  nullptr, nullptr, 0,
        nullptr, Q, S);

    // 6) P row-major = Q^T
    transpose_bf16<<<dim3(NN_/32, NN_/32), dim3(32, 8)>>>(Q, Prm, NN_, NN_);

    // 7) GEMM-4 (HMMA, wf split): PW = P@wfh + P@wfl  (row-major fp32)
    tensor_gemm<1><<<dim3(OUTF/128, NN_/128), 256, DSM_BYTES>>>(
        Prm, wfTh, NN_/64,  Prm, wfTl, NN_/64,  nullptr, nullptr, 0,
        PW, nullptr, nullptr);

    // 8) out[k][j] = wf[j][k]*PW[j][k]/nc[k]^2
    finalize_kernel<<<dim3(NN_/32, NN_/32), dim3(32, 8)>>>(wf, PW, nc, out);
}